// round 14
// baseline (speedup 1.0000x reference)
#include <cuda_runtime.h>
#include <cuda_bf16.h>

// ValScores: per-class mean of preds rows (segment reduction by label) + EMA.
//   out[c,:] = cnt[c]>0 ? 0.1*mean_c(preds) + 0.9*val_preds[c,:] : val_preds[c,:]
//
// Converged structure (13 rounds of evidence; best 92.9us @ R13):
//   - k_scatter: KSUB=8 bucket scatter, cursor doubles as count.
//   - k_reduce : one CTA per class, 256 threads, pinned (256,8) -> 32 regs,
//     grid=1000 single wave; whole contiguous 4000B rows, 4x float4 __ldcs
//     unroll (32-reg MLP max). Reduce = 90.5us @ DRAM 74.9% — the pattern
//     ceiling for random-4KB-gather segment reduction on GB300.
//   Failed alternatives: ticket stealing, column split, row split (+spin or
//   +REDG), fused grid barrier, 8-row unroll, shfl scan (reg creep).
// This round: scatter de-vectorized to 1 elem/thread (512 CTAs, 27 warps/SM)
// so each ATOMG ~318cyc hides behind warp parallelism instead of a 4-deep
// serial chain on 8x fewer warps. Reduce byte-identical to R13.

#define C_MAX   1024
#define KSUB    8
#define CAP     256            // per sub-list capacity (expected ~16 +- 4)
#define SMAX    (KSUB * CAP)   // 2048 indices, 8KB smem
#define GAMMA   0.9f
#define ONE_MINUS_GAMMA 0.1f

__device__ int g_cursor[C_MAX * KSUB];        // zero-init at module load
__device__ int g_rowidx[C_MAX * KSUB * CAP];  // 8 MB scratch

// ---------------------------------------------------------------------------
// Scatter: 1 element/thread, one independent atomic each; grid = N/256 CTAs
// gives ~27 warps/SM of latency hiding. Sub-cursor from element-index low
// bits -> adjacent same-class elements hit different L2 lines.
// ---------------------------------------------------------------------------
__global__ __launch_bounds__(256) void k_scatter(const int* __restrict__ labels, int N) {
    int i = blockIdx.x * blockDim.x + threadIdx.x;
    if (i >= N) return;
    int b = labels[i] * KSUB + (i & (KSUB - 1));
    int p = atomicAdd(&g_cursor[b], 1);
    if (p < CAP) g_rowidx[b * CAP + p] = i;
}

// ---------------------------------------------------------------------------
// Reduce: one CTA per class, 256 threads, pinned to 8 CTAs/SM (<=32 regs).
// Thread t owns cols [4t, 4t+3]. Hot path identical to the 92.9us winner.
// ---------------------------------------------------------------------------
__global__ __launch_bounds__(256, 8) void k_reduce_v4(
    const float* __restrict__ preds,
    const float* __restrict__ val_preds,
    float* __restrict__ out,
    int C)
{
    int c   = blockIdx.x;
    int tid = threadIdx.x;

    __shared__ int s_base[KSUB + 1];
    __shared__ int s_idx[SMAX];

    // Per-sub counts -> prefix (KSUB=8, done by thread 0; trivial).
    if (tid == 0) {
        int tot = 0;
        #pragma unroll
        for (int s = 0; s < KSUB; ++s) {
            s_base[s] = tot;
            int cs = g_cursor[c * KSUB + s];
            tot += (cs < CAP ? cs : CAP);
        }
        s_base[KSUB] = tot;
    }
    __syncthreads();

    // Cooperative stage of all row indices into smem (compacted).
    #pragma unroll
    for (int s = 0; s < KSUB; ++s) {
        int lo = s_base[s], cs = s_base[s + 1] - lo;
        const int* src = &g_rowidx[(c * KSUB + s) * CAP];
        for (int j = tid; j < cs; j += 256) s_idx[lo + j] = src[j];
    }
    __syncthreads();

    // Sole reader of this class's cursors -> reset for next graph replay.
    if (tid < KSUB) g_cursor[c * KSUB + tid] = 0;

    int cnt  = s_base[KSUB];
    int col4 = tid * 4;
    if (col4 >= C) return;

    float ax = 0.f, ay = 0.f, az = 0.f, aw = 0.f;
    int r = 0;
    // 4 independent 16B streaming loads in flight per thread
    // (the 32-register MLP maximum that preserves 8 CTAs/SM).
    for (; r + 3 < cnt; r += 4) {
        const float4* p0 = (const float4*)(preds + (size_t)s_idx[r + 0] * C + col4);
        const float4* p1 = (const float4*)(preds + (size_t)s_idx[r + 1] * C + col4);
        const float4* p2 = (const float4*)(preds + (size_t)s_idx[r + 2] * C + col4);
        const float4* p3 = (const float4*)(preds + (size_t)s_idx[r + 3] * C + col4);
        float4 v0 = __ldcs(p0);
        float4 v1 = __ldcs(p1);
        float4 v2 = __ldcs(p2);
        float4 v3 = __ldcs(p3);
        ax += v0.x; ay += v0.y; az += v0.z; aw += v0.w;
        ax += v1.x; ay += v1.y; az += v1.z; aw += v1.w;
        ax += v2.x; ay += v2.y; az += v2.z; aw += v2.w;
        ax += v3.x; ay += v3.y; az += v3.z; aw += v3.w;
    }
    for (; r < cnt; ++r) {
        float4 v = __ldcs((const float4*)(preds + (size_t)s_idx[r] * C + col4));
        ax += v.x; ay += v.y; az += v.z; aw += v.w;
    }

    float4 vp = *(const float4*)(val_preds + (size_t)c * C + col4);
    float4 o;
    if (cnt > 0) {
        float inv = ONE_MINUS_GAMMA / (float)cnt;
        o.x = ax * inv + GAMMA * vp.x;
        o.y = ay * inv + GAMMA * vp.y;
        o.z = az * inv + GAMMA * vp.z;
        o.w = aw * inv + GAMMA * vp.w;
    } else {
        o = vp;
    }
    *(float4*)(out + (size_t)c * C + col4) = o;
}

// Scalar-column fallback (C % 4 != 0 or C > 1024): 1 CTA per class.
__global__ __launch_bounds__(256) void k_reduce_s(
    const float* __restrict__ preds,
    const float* __restrict__ val_preds,
    float* __restrict__ out,
    int C)
{
    int c   = blockIdx.x;
    int tid = threadIdx.x;

    __shared__ int s_base[KSUB + 1];
    __shared__ int s_idx[SMAX];

    if (tid == 0) {
        int tot = 0;
        #pragma unroll
        for (int s = 0; s < KSUB; ++s) {
            s_base[s] = tot;
            int cs = g_cursor[c * KSUB + s];
            tot += (cs < CAP ? cs : CAP);
        }
        s_base[KSUB] = tot;
    }
    __syncthreads();
    #pragma unroll
    for (int s = 0; s < KSUB; ++s) {
        int lo = s_base[s], cs = s_base[s + 1] - lo;
        const int* src = &g_rowidx[(c * KSUB + s) * CAP];
        for (int j = tid; j < cs; j += 256) s_idx[lo + j] = src[j];
    }
    __syncthreads();
    if (tid < KSUB) g_cursor[c * KSUB + tid] = 0;

    int cnt = s_base[KSUB];
    for (int col = tid; col < C; col += 256) {
        float acc = 0.f;
        for (int r = 0; r < cnt; ++r)
            acc += __ldcs(preds + (size_t)s_idx[r] * C + col);
        float vp = val_preds[(size_t)c * C + col];
        out[(size_t)c * C + col] =
            (cnt > 0) ? (ONE_MINUS_GAMMA * acc / (float)cnt + GAMMA * vp) : vp;
    }
}

extern "C" void kernel_launch(void* const* d_in, const int* in_sizes, int n_in,
                              void* d_out, int out_size) {
    const float* preds     = (const float*)d_in[0];
    const int*   labels    = (const int*)  d_in[1];
    const float* val_preds = (const float*)d_in[2];
    float*       out       = (float*)d_out;

    const int N = in_sizes[1];       // 131072
    const int C = in_sizes[0] / N;   // 1000

    k_scatter<<<(N + 255) / 256, 256>>>(labels, N);

    if ((C % 4) == 0 && C <= C_MAX) {
        k_reduce_v4<<<C, 256>>>(preds, val_preds, out, C);
    } else {
        k_reduce_s<<<C, 256>>>(preds, val_preds, out, C);
    }
}